// round 2
// baseline (speedup 1.0000x reference)
#include <cuda_runtime.h>
#include <stdint.h>

// Problem constants
#define NBINS      32
#define NCH        64            // B*C = 8*8
#define HW         65536         // 256*256 pixels per channel
#define NSUB       2048          // fine histogram sub-bins over [0,1)
#define CTAS_PER_CH 8
#define NCTA1      (NCH * CTAS_PER_CH)      // 512
#define F4_PER_CTA ((HW / 4) / CTAS_PER_CH) // 2048 float4 per CTA
#define PAD        320           // +-5 sigma window = +-320 sub-bins
#define WIN        (2 * PAD)     // 640
#define CHUNK      (WIN / 8)     // 80 terms per thread (8 threads per bin)

#define AMPL   0.3989472f        // ER/RATIO = 1/2.5066
#define INV31  (1.0f / 31.0f)    // bin spacing (linspace(0,1,32))
#define K512   512.0f            // 1/(2*sigma^2), sigma = 1/32
#define DELTA  (1.0f / 2048.0f)  // sub-bin width

// Packed per-CTA partial histograms: two u16 counts per u32 word.
// 512 slabs * 1024 words * 4B = 2 MB scratch. Max count per slab bin = 8192 < 65536.
__device__ unsigned int g_pack[NCTA1 * (NSUB / 2)];

// ---------------------------------------------------------------------------
// Kernel 1: fine count histogram per CTA slice (shared-memory atomics),
// flushed as packed u16 pairs to a private slab (every word overwritten each
// launch -> no zeroing needed, deterministic, replay-safe).
// Also zeroes the 2048-float output (stream order guarantees it precedes
// conv_kernel's atomics).
// ---------------------------------------------------------------------------
__global__ __launch_bounds__(256, 8)
void hist_kernel(const float* __restrict__ x, float* __restrict__ out)
{
    __shared__ unsigned int h[NSUB];
    const int tid = threadIdx.x;

    #pragma unroll
    for (int i = tid; i < NSUB; i += 256) h[i] = 0u;

    if (blockIdx.x < 8)                         // 8 CTAs x 256 threads = 2048
        out[blockIdx.x * 256 + tid] = 0.0f;

    __syncthreads();

    const float4* __restrict__ p =
        reinterpret_cast<const float4*>(x) + (size_t)blockIdx.x * F4_PER_CTA;

    #pragma unroll
    for (int i = tid; i < F4_PER_CTA; i += 256) {
        float4 v = p[i];
        int b0 = (int)(v.x * (float)NSUB);
        int b1 = (int)(v.y * (float)NSUB);
        int b2 = (int)(v.z * (float)NSUB);
        int b3 = (int)(v.w * (float)NSUB);
        b0 = min(NSUB - 1, max(0, b0));
        b1 = min(NSUB - 1, max(0, b1));
        b2 = min(NSUB - 1, max(0, b2));
        b3 = min(NSUB - 1, max(0, b3));
        atomicAdd(&h[b0], 1u);
        atomicAdd(&h[b1], 1u);
        atomicAdd(&h[b2], 1u);
        atomicAdd(&h[b3], 1u);
    }
    __syncthreads();

    unsigned int* __restrict__ slab = g_pack + (size_t)blockIdx.x * (NSUB / 2);
    #pragma unroll
    for (int i = tid; i < NSUB / 2; i += 256)
        slab[i] = (h[2 * i] & 0xFFFFu) | (h[2 * i + 1] << 16);
}

// ---------------------------------------------------------------------------
// Kernel 2: one CTA per SLAB (512 CTAs). Unpack own slab into shared
// (zero-padded by +-PAD), Gaussian-window each of the 32 output bins using
// the lattice recurrence (2 expf per 80-term chunk), atomically accumulate
// the per-slab partial into out[ch*32+j].
// ---------------------------------------------------------------------------
__global__ __launch_bounds__(256, 8)
void conv_kernel(float* __restrict__ out)
{
    __shared__ float h[NSUB + 2 * PAD];   // 2688 floats
    const int tid = threadIdx.x;
    const int ch  = blockIdx.x >> 3;      // slab -> channel

    const unsigned int* __restrict__ slab =
        g_pack + (size_t)blockIdx.x * (NSUB / 2);

    #pragma unroll
    for (int i = tid; i < NSUB / 2; i += 256) {
        unsigned int v = slab[i];
        h[PAD + 2 * i]     = (float)(v & 0xFFFFu);
        h[PAD + 2 * i + 1] = (float)(v >> 16);
    }
    #pragma unroll
    for (int i = tid; i < PAD; i += 256) {
        h[i] = 0.0f;
        h[PAD + NSUB + i] = 0.0f;
    }
    __syncthreads();

    const int j   = tid >> 3;   // output bin 0..31
    const int sub = tid & 7;    // 8 threads per bin

    const float cj = (float)j * INV31;
    const int m0 = (int)(cj * (float)NSUB) - PAD + sub * CHUNK;

    const float x0 = ((float)m0 + 0.5f) * DELTA;
    const float d0 = x0 - cj;

    float w = __expf(-d0 * d0 * K512);
    float r = __expf(-K512 * DELTA * (2.0f * d0 + DELTA));
    const float g = __expf(-2.0f * K512 * DELTA * DELTA);

    float acc = 0.0f;
    #pragma unroll
    for (int k = 0; k < CHUNK; k++) {
        acc = fmaf(h[m0 + k + PAD], w, acc);
        w *= r;
        r *= g;
    }

    // reduce the 8-thread group (contiguous lanes)
    #pragma unroll
    for (int off = 4; off > 0; off >>= 1)
        acc += __shfl_down_sync(0xFFFFFFFFu, acc, off, 8);

    if (sub == 0)
        atomicAdd(&out[ch * NBINS + j], acc * AMPL);
}

// ---------------------------------------------------------------------------
extern "C" void kernel_launch(void* const* d_in, const int* in_sizes, int n_in,
                              void* d_out, int out_size)
{
    const float* x = (const float*)d_in[0];   // [8,8,256,256] fp32
    float* out = (float*)d_out;               // [8,256,1,1] = 2048 fp32

    hist_kernel<<<NCTA1, 256>>>(x, out);
    conv_kernel<<<NCTA1, 256>>>(out);
}

// round 3
// speedup vs baseline: 1.2440x; 1.2440x over previous
#include <cuda_runtime.h>
#include <stdint.h>

// Problem constants
#define NBINS      32
#define NCH        64            // B*C = 8*8
#define HW         65536         // 256*256 pixels per channel
#define NSUB       2048          // fine histogram sub-bins over [0,1)
#define CTAS_PER_CH 8
#define NCTA      (NCH * CTAS_PER_CH)       // 512
#define F4_PER_CTA ((HW / 4) / CTAS_PER_CH) // 2048 float4 per CTA
#define PAD        320           // +-5 sigma window = +-320 sub-bins
#define WIN        (2 * PAD)     // 640
#define NSTEP      (WIN / 32)    // 20 strided steps of 32 lanes

#define AMPL   0.3989472f        // ER/RATIO = 1/2.5066
#define INV31  (1.0f / 31.0f)    // bin spacing (linspace(0,1,32))
#define K512   512.0f            // 1/(2*sigma^2), sigma = 1/32
#define DELTA  (1.0f / 2048.0f)  // sub-bin width
#define STEP32 (32.0f * DELTA)   // lane stride in x

// ---------------------------------------------------------------------------
// Kernel 0: zero the output (must complete before fused kernel's atomics).
// ---------------------------------------------------------------------------
__global__ void zero_kernel(float* __restrict__ out)
{
    out[blockIdx.x * 1024 + threadIdx.x] = 0.0f;
}

// ---------------------------------------------------------------------------
// Fused kernel: one CTA per slab (1/8 channel).
// Phase 1: fine count histogram of own slice via shared atomics.
// Phase 2: convert counts to a +-PAD zero-padded float array in shared.
// Phase 3: warp-per-bin Gaussian window sum; 32 lanes read CONSECUTIVE
//          shared words (conflict-free), stepping 32 sub-bins per iter
//          with the lattice recurrence:
//            w += h*w; w *= r; r *= gS,  gS = exp(-2*K*(32d)^2) = exp(-0.25)
//          -> 2 expf per (bin, lane).
// Per-slab partials accumulate into out via atomicAdd (16K total, noise).
// ---------------------------------------------------------------------------
__global__ __launch_bounds__(256, 8)
void fused_kernel(const float* __restrict__ x, float* __restrict__ out)
{
    __shared__ unsigned int hc[NSUB];        // 8 KB counts
    __shared__ float        hf[NSUB + WIN];  // 10.5 KB padded floats

    const int tid = threadIdx.x;

    #pragma unroll
    for (int i = tid; i < NSUB; i += 256) hc[i] = 0u;
    __syncthreads();

    // ---- Phase 1: histogram own slice -------------------------------------
    const float4* __restrict__ p =
        reinterpret_cast<const float4*>(x) + (size_t)blockIdx.x * F4_PER_CTA;

    #pragma unroll
    for (int i = tid; i < F4_PER_CTA; i += 256) {
        float4 v = p[i];
        int b0 = (int)(v.x * (float)NSUB);
        int b1 = (int)(v.y * (float)NSUB);
        int b2 = (int)(v.z * (float)NSUB);
        int b3 = (int)(v.w * (float)NSUB);
        b0 = min(NSUB - 1, max(0, b0));
        b1 = min(NSUB - 1, max(0, b1));
        b2 = min(NSUB - 1, max(0, b2));
        b3 = min(NSUB - 1, max(0, b3));
        atomicAdd(&hc[b0], 1u);
        atomicAdd(&hc[b1], 1u);
        atomicAdd(&hc[b2], 1u);
        atomicAdd(&hc[b3], 1u);
    }
    __syncthreads();

    // ---- Phase 2: counts -> padded floats ---------------------------------
    #pragma unroll
    for (int i = tid; i < NSUB; i += 256) hf[PAD + i] = (float)hc[i];
    #pragma unroll
    for (int i = tid; i < PAD; i += 256) {
        hf[i] = 0.0f;
        hf[PAD + NSUB + i] = 0.0f;
    }
    __syncthreads();

    // ---- Phase 3: warp-per-bin convolution --------------------------------
    const int warp = tid >> 5;
    const int lane = tid & 31;
    const int ch   = blockIdx.x >> 3;
    const float gS = __expf(-2.0f * K512 * STEP32 * STEP32);  // exp(-0.25)

    #pragma unroll
    for (int b = 0; b < 4; b++) {
        const int j = warp + 8 * b;                 // bin 0..31
        const float cj = (float)j * INV31;
        const int icenter = (int)(cj * (float)NSUB);
        // first sample of this lane: sub-bin m = icenter - PAD + lane
        const float d0 = ((float)(icenter - PAD + lane) + 0.5f) * DELTA - cj;

        float w = __expf(-d0 * d0 * K512);
        float r = __expf(-K512 * STEP32 * (2.0f * d0 + STEP32));

        int idx = icenter + lane;                   // = PAD + m0 + lane
        float acc = 0.0f;
        #pragma unroll
        for (int i = 0; i < NSTEP; i++) {
            acc = fmaf(hf[idx], w, acc);
            w *= r;
            r *= gS;
            idx += 32;
        }

        // full-warp reduce
        #pragma unroll
        for (int off = 16; off > 0; off >>= 1)
            acc += __shfl_down_sync(0xFFFFFFFFu, acc, off);

        if (lane == 0)
            atomicAdd(&out[ch * NBINS + j], acc * AMPL);
    }
}

// ---------------------------------------------------------------------------
extern "C" void kernel_launch(void* const* d_in, const int* in_sizes, int n_in,
                              void* d_out, int out_size)
{
    const float* x = (const float*)d_in[0];   // [8,8,256,256] fp32
    float* out = (float*)d_out;               // [8,256,1,1] = 2048 fp32

    zero_kernel<<<2, 1024>>>(out);
    fused_kernel<<<NCTA, 256>>>(x, out);
}